// round 2
// baseline (speedup 1.0000x reference)
#include <cuda_runtime.h>

// Problem constants
#define BB 4
#define SS 2048
#define DD 1024
#define HH 16
#define DH 64
#define MTOT (BB*SS)          // 8192 rows
#define LOG2E 1.4426950408889634f

// Scratch (allocation-free rule: __device__ globals)
__device__ float g_q[(size_t)MTOT * DD];
__device__ float g_k[(size_t)MTOT * DD];
__device__ float g_v[(size_t)MTOT * DD];
__device__ float g_o[(size_t)MTOT * DD];

// ---------------------------------------------------------------------------
// Tiled GEMM + bias: C[M=8192, N=1024] = A[8192,1024] * W + bias
// HEADED=true: W is [H, D, 64]  (per-head weights; block col == head)
// HEADED=false: W is [1024, 1024] row-major
// Tile: 64x64, BK=16, 256 threads, 4x4 micro-tile per thread.
// ---------------------------------------------------------------------------
template<bool HEADED>
__global__ __launch_bounds__(256)
void gemm_bias(const float* __restrict__ A, const float* __restrict__ W,
               const float* __restrict__ bias, float* __restrict__ C)
{
    const int K = 1024, N = 1024;
    __shared__ float As[16][64];
    __shared__ float Bs[16][64];
    int tid = threadIdx.x;
    int bn = blockIdx.x;     // 0..15
    int bm = blockIdx.y;     // 0..127
    int tx = tid & 15, ty = tid >> 4;

    const float* Wp;
    int ldw;
    if (HEADED) { Wp = W + (size_t)bn * K * 64; ldw = 64; }   // head bn, [K,64]
    else        { Wp = W + bn * 64;            ldw = N;  }

    float acc[4][4];
    #pragma unroll
    for (int i = 0; i < 4; i++)
        #pragma unroll
        for (int j = 0; j < 4; j++) acc[i][j] = 0.f;

    int ar  = tid >> 2;      // A tile row 0..63
    int ac4 = tid & 3;       // A float4 col 0..3 (covers k 0..15)
    int wr  = tid >> 4;      // W tile row (k) 0..15
    int wc4 = tid & 15;      // W float4 col 0..15

    const float* Ap = A + (size_t)(bm * 64 + ar) * K + ac4 * 4;

    for (int kt = 0; kt < K; kt += 16) {
        float4 av = *(const float4*)(Ap + kt);
        float4 wv = *(const float4*)(Wp + (size_t)(kt + wr) * ldw + wc4 * 4);
        As[ac4 * 4 + 0][ar] = av.x;
        As[ac4 * 4 + 1][ar] = av.y;
        As[ac4 * 4 + 2][ar] = av.z;
        As[ac4 * 4 + 3][ar] = av.w;
        *(float4*)&Bs[wr][wc4 * 4] = wv;
        __syncthreads();
        #pragma unroll
        for (int kk = 0; kk < 16; kk++) {
            float4 a = *(const float4*)&As[kk][ty * 4];
            float4 b = *(const float4*)&Bs[kk][tx * 4];
            float ax[4] = {a.x, a.y, a.z, a.w};
            float bx[4] = {b.x, b.y, b.z, b.w};
            #pragma unroll
            for (int i = 0; i < 4; i++)
                #pragma unroll
                for (int j = 0; j < 4; j++) acc[i][j] += ax[i] * bx[j];
        }
        __syncthreads();
    }

    #pragma unroll
    for (int i = 0; i < 4; i++) {
        int m = bm * 64 + ty * 4 + i;
        int n = bn * 64 + tx * 4;
        float4 outv;
        outv.x = acc[i][0] + bias[n + 0];
        outv.y = acc[i][1] + bias[n + 1];
        outv.z = acc[i][2] + bias[n + 2];
        outv.w = acc[i][3] + bias[n + 3];
        *(float4*)(C + (size_t)m * N + n) = outv;
    }
}

// ---------------------------------------------------------------------------
// Flash-attention (fp32): one thread per query row, 128 rows per block.
// K/V tiles of 64 rows in SMEM; scores processed in chunks of 16 (online
// softmax) to bound register pressure.
// q/k/v layout: [b, s, h, e] (row stride H*DH = 1024)
// ---------------------------------------------------------------------------
__global__ __launch_bounds__(128)
void attn_kernel(const float* __restrict__ q, const float* __restrict__ k,
                 const float* __restrict__ v, float* __restrict__ o)
{
    __shared__ float Ks[64][64];
    __shared__ float Vs[64][64];
    int b = blockIdx.z, h = blockIdx.y;
    int tid = threadIdx.x;
    int row = blockIdx.x * 128 + tid;
    const int rowstride = HH * DH;   // 1024

    const float* qp = q + ((size_t)(b * SS + row) * HH + h) * DH;
    float qreg[64];
    #pragma unroll
    for (int e4 = 0; e4 < 16; e4++) {
        float4 t = ((const float4*)qp)[e4];
        qreg[e4 * 4 + 0] = t.x; qreg[e4 * 4 + 1] = t.y;
        qreg[e4 * 4 + 2] = t.z; qreg[e4 * 4 + 3] = t.w;
    }
    float acc[64];
    #pragma unroll
    for (int e = 0; e < 64; e++) acc[e] = 0.f;
    float mrun = -1e30f, lrun = 0.f;

    const float* kb0 = k + ((size_t)b * SS * HH + h) * DH;
    const float* vb0 = v + ((size_t)b * SS * HH + h) * DH;

    for (int t0 = 0; t0 < SS; t0 += 64) {
        __syncthreads();
        #pragma unroll
        for (int i = 0; i < 8; i++) {
            int idx = tid + i * 128;          // 0..1023 float4 slots
            int r = idx >> 4, c4 = idx & 15;
            ((float4*)&Ks[r][0])[c4] =
                ((const float4*)(kb0 + (size_t)(t0 + r) * rowstride))[c4];
            ((float4*)&Vs[r][0])[c4] =
                ((const float4*)(vb0 + (size_t)(t0 + r) * rowstride))[c4];
        }
        __syncthreads();

        #pragma unroll 1
        for (int jc = 0; jc < 4; jc++) {     // 4 chunks of 16 keys
            float s[16];
            #pragma unroll
            for (int j = 0; j < 16; j++) {
                float d = 0.f;
                #pragma unroll
                for (int e4 = 0; e4 < 16; e4++) {
                    float4 kv = ((const float4*)&Ks[jc * 16 + j][0])[e4];
                    d += qreg[e4 * 4 + 0] * kv.x;
                    d += qreg[e4 * 4 + 1] * kv.y;
                    d += qreg[e4 * 4 + 2] * kv.z;
                    d += qreg[e4 * 4 + 3] * kv.w;
                }
                s[j] = d * 0.125f;           // 1/sqrt(64)
            }
            float mt = mrun;
            #pragma unroll
            for (int j = 0; j < 16; j++) mt = fmaxf(mt, s[j]);
            float corr = __expf(mrun - mt);
            mrun = mt;
            float psum = 0.f;
            #pragma unroll
            for (int j = 0; j < 16; j++) { s[j] = __expf(s[j] - mt); psum += s[j]; }
            lrun = lrun * corr + psum;
            #pragma unroll
            for (int e = 0; e < 64; e++) acc[e] *= corr;
            #pragma unroll
            for (int j = 0; j < 16; j++) {
                float pj = s[j];
                #pragma unroll
                for (int e4 = 0; e4 < 16; e4++) {
                    float4 vv = ((const float4*)&Vs[jc * 16 + j][0])[e4];
                    acc[e4 * 4 + 0] += pj * vv.x;
                    acc[e4 * 4 + 1] += pj * vv.y;
                    acc[e4 * 4 + 2] += pj * vv.z;
                    acc[e4 * 4 + 3] += pj * vv.w;
                }
            }
        }
    }

    float inv = 1.f / lrun;
    float* op = o + ((size_t)(b * SS + row) * HH + h) * DH;
    #pragma unroll
    for (int e4 = 0; e4 < 16; e4++) {
        float4 t;
        t.x = acc[e4 * 4 + 0] * inv; t.y = acc[e4 * 4 + 1] * inv;
        t.z = acc[e4 * 4 + 2] * inv; t.w = acc[e4 * 4 + 3] * inv;
        ((float4*)op)[e4] = t;
    }
}

// ---------------------------------------------------------------------------
// Launch
// inputs: queries, keys, values, Wq, bq, Wk, bk, Wv, bv, Wo, bo
// ---------------------------------------------------------------------------
extern "C" void kernel_launch(void* const* d_in, const int* in_sizes, int n_in,
                              void* d_out, int out_size)
{
    (void)in_sizes; (void)n_in; (void)out_size;
    const float* queries = (const float*)d_in[0];
    const float* keys    = (const float*)d_in[1];
    const float* values  = (const float*)d_in[2];
    const float* Wq = (const float*)d_in[3];
    const float* bq = (const float*)d_in[4];
    const float* Wk = (const float*)d_in[5];
    const float* bk = (const float*)d_in[6];
    const float* Wv = (const float*)d_in[7];
    const float* bv = (const float*)d_in[8];
    const float* Wo = (const float*)d_in[9];
    const float* bo = (const float*)d_in[10];
    float* out = (float*)d_out;

    float *pq, *pk, *pv, *po;
    cudaGetSymbolAddress((void**)&pq, g_q);
    cudaGetSymbolAddress((void**)&pk, g_k);
    cudaGetSymbolAddress((void**)&pv, g_v);
    cudaGetSymbolAddress((void**)&po, g_o);

    dim3 ggrid(16, 128);            // N/64 x M/64
    gemm_bias<true><<<ggrid, 256>>>(queries, Wq, bq, pq);
    gemm_bias<true><<<ggrid, 256>>>(keys,    Wk, bk, pk);
    gemm_bias<true><<<ggrid, 256>>>(values,  Wv, bv, pv);

    dim3 agrid(SS / 128, HH, BB);   // (16, 16, 4)
    attn_kernel<<<agrid, 128>>>(pq, pk, pv, po);

    gemm_bias<false><<<ggrid, 256>>>(po, Wo, bo, out);
}

// round 3
// speedup vs baseline: 3.6668x; 3.6668x over previous
#include <cuda_runtime.h>
#include <cstdint>

#define BB 4
#define SS 2048
#define HH 16
#define DH 64

__device__ float g_q[(size_t)8192*1024];
__device__ float g_k[(size_t)8192*1024];
__device__ float g_v[(size_t)8192*1024];
__device__ float g_o[(size_t)8192*1024];

__device__ __forceinline__ uint32_t f2tf(float f){
    uint32_t u; asm("cvt.rna.tf32.f32 %0, %1;" : "=r"(u) : "f"(f)); return u;
}
__device__ __forceinline__ void mma8(float* c, uint32_t a0,uint32_t a1,uint32_t a2,uint32_t a3,
                                     uint32_t b0,uint32_t b1){
    asm volatile("mma.sync.aligned.m16n8k8.row.col.f32.tf32.tf32.f32 "
                 "{%0,%1,%2,%3},{%4,%5,%6,%7},{%8,%9},{%0,%1,%2,%3};"
        : "+f"(c[0]),"+f"(c[1]),"+f"(c[2]),"+f"(c[3])
        : "r"(a0),"r"(a1),"r"(a2),"r"(a3),"r"(b0),"r"(b1));
}

// ---------------------------------------------------------------------------
// tf32 GEMM + bias: C[8192,1024] = A * W + bias.  Tile 128x128, BK=16,
// 256 threads = 8 warps (2m x 4n), warp tile 64x32.
// HEADED: W is [16][1024][64]; else [1024][1024].
// ---------------------------------------------------------------------------
template<bool HEADED>
__global__ __launch_bounds__(256)
void gemm_tf32(const float* __restrict__ A, const float* __restrict__ W,
               const float* __restrict__ bias, float* __restrict__ C)
{
    const int K = 1024, N = 1024;
    __shared__ uint32_t As[128][20];
    __shared__ uint32_t Bs[16][136];
    int tid = threadIdx.x, lane = tid & 31, warp = tid >> 5;
    int wm = warp >> 2, wn = warp & 3;
    int grp = lane >> 2, tig = lane & 3;
    int bn = blockIdx.x, bm = blockIdx.y;

    float acc[4][4][4] = {};

    int ar[2], ac[2], br[2], bc[2];
    #pragma unroll
    for (int i = 0; i < 2; i++){
        int v = tid + i*256;
        ar[i] = v >> 2;  ac[i] = (v & 3) * 4;
        br[i] = v >> 5;  bc[i] = (v & 31) * 4;
    }

    float4 pa[2], pb[2];
    #pragma unroll
    for (int i = 0; i < 2; i++){
        pa[i] = *(const float4*)(A + (size_t)(bm*128 + ar[i])*K + ac[i]);
        int n = bn*128 + bc[i];
        const float* wp = HEADED ? (W + ((size_t)(n >> 6)*K + br[i])*64 + (n & 63))
                                 : (W + (size_t)br[i]*N + n);
        pb[i] = *(const float4*)wp;
    }

    for (int kt = 0; kt < K; kt += 16){
        __syncthreads();
        #pragma unroll
        for (int i = 0; i < 2; i++){
            uint4 va = make_uint4(f2tf(pa[i].x), f2tf(pa[i].y), f2tf(pa[i].z), f2tf(pa[i].w));
            *(uint4*)&As[ar[i]][ac[i]] = va;
            uint4 vb = make_uint4(f2tf(pb[i].x), f2tf(pb[i].y), f2tf(pb[i].z), f2tf(pb[i].w));
            *(uint4*)&Bs[br[i]][bc[i]] = vb;
        }
        __syncthreads();
        if (kt + 16 < K){
            #pragma unroll
            for (int i = 0; i < 2; i++){
                pa[i] = *(const float4*)(A + (size_t)(bm*128 + ar[i])*K + (kt+16) + ac[i]);
                int n = bn*128 + bc[i];
                const float* wp = HEADED ? (W + ((size_t)(n >> 6)*K + (kt+16+br[i]))*64 + (n & 63))
                                         : (W + (size_t)(kt+16+br[i])*N + n);
                pb[i] = *(const float4*)wp;
            }
        }
        #pragma unroll
        for (int kc = 0; kc < 2; kc++){
            uint32_t af[4][4];
            #pragma unroll
            for (int mt = 0; mt < 4; mt++){
                int row = wm*64 + mt*16, col = kc*8;
                af[mt][0] = As[row+grp  ][col+tig  ];
                af[mt][1] = As[row+grp+8][col+tig  ];
                af[mt][2] = As[row+grp  ][col+tig+4];
                af[mt][3] = As[row+grp+8][col+tig+4];
            }
            #pragma unroll
            for (int nt = 0; nt < 4; nt++){
                uint32_t b0 = Bs[kc*8+tig  ][wn*32 + nt*8 + grp];
                uint32_t b1 = Bs[kc*8+tig+4][wn*32 + nt*8 + grp];
                #pragma unroll
                for (int mt = 0; mt < 4; mt++)
                    mma8(acc[mt][nt], af[mt][0], af[mt][1], af[mt][2], af[mt][3], b0, b1);
            }
        }
    }

    #pragma unroll
    for (int mt = 0; mt < 4; mt++){
        int row = bm*128 + wm*64 + mt*16 + grp;
        #pragma unroll
        for (int nt = 0; nt < 4; nt++){
            int col = bn*128 + wn*32 + nt*8 + 2*tig;
            float bx = bias[col], by = bias[col+1];
            *(float2*)(C + (size_t)row*N + col) =
                make_float2(acc[mt][nt][0] + bx, acc[mt][nt][1] + by);
            *(float2*)(C + (size_t)(row+8)*N + col) =
                make_float2(acc[mt][nt][2] + bx, acc[mt][nt][3] + by);
        }
    }
}

// ---------------------------------------------------------------------------
// Flash attention, tf32 mma. Block = 128 threads (4 warps), 64 q rows
// (16 per warp). Key tile = 32. Q frags in registers (scale folded).
// Ks/Vs [32][64] stride 68; P per-warp [16][32] stride 36.
// q/k/v layout [b,s,h,e].
// ---------------------------------------------------------------------------
__global__ __launch_bounds__(128)
void attn_tf32(const float* __restrict__ q, const float* __restrict__ k,
               const float* __restrict__ v, float* __restrict__ o)
{
    __shared__ uint32_t Ks[32][68];
    __shared__ uint32_t Vs[32][68];
    __shared__ uint32_t Ps[4][16][36];
    int tid = threadIdx.x, lane = tid & 31, warp = tid >> 5;
    int grp = lane >> 2, tig = lane & 3;
    int b = blockIdx.z, h = blockIdx.y, q0 = blockIdx.x * 64;
    int qrow = q0 + warp*16;

    uint32_t qf[8][4];
    #pragma unroll
    for (int kc = 0; kc < 8; kc++){
        size_t r0 = ((size_t)(b*SS + qrow + grp    )*HH + h)*DH;
        size_t r1 = ((size_t)(b*SS + qrow + grp + 8)*HH + h)*DH;
        qf[kc][0] = f2tf(q[r0 + kc*8 + tig    ] * 0.125f);
        qf[kc][1] = f2tf(q[r1 + kc*8 + tig    ] * 0.125f);
        qf[kc][2] = f2tf(q[r0 + kc*8 + tig + 4] * 0.125f);
        qf[kc][3] = f2tf(q[r1 + kc*8 + tig + 4] * 0.125f);
    }

    float oacc[8][4] = {};
    float mrun[2] = {-1e30f, -1e30f}, lrun[2] = {0.f, 0.f};
    const float* kg = k + ((size_t)b*SS*HH + h)*DH;
    const float* vg = v + ((size_t)b*SS*HH + h)*DH;

    for (int kt = 0; kt < SS; kt += 32){
        __syncthreads();
        #pragma unroll
        for (int i = 0; i < 4; i++){
            int v4 = tid + i*128;
            int r = v4 >> 4, c4 = (v4 & 15)*4;
            float4 t = *(const float4*)(kg + (size_t)(kt + r)*1024 + c4);
            *(uint4*)&Ks[r][c4] = make_uint4(f2tf(t.x), f2tf(t.y), f2tf(t.z), f2tf(t.w));
            float4 u = *(const float4*)(vg + (size_t)(kt + r)*1024 + c4);
            *(uint4*)&Vs[r][c4] = make_uint4(f2tf(u.x), f2tf(u.y), f2tf(u.z), f2tf(u.w));
        }
        __syncthreads();

        // S = Q K^T : 16q x 32keys per warp
        float sacc[4][4] = {};
        #pragma unroll
        for (int kc = 0; kc < 8; kc++)
            #pragma unroll
            for (int nt = 0; nt < 4; nt++){
                uint32_t b0 = Ks[nt*8 + grp][kc*8 + tig    ];
                uint32_t b1 = Ks[nt*8 + grp][kc*8 + tig + 4];
                mma8(sacc[nt], qf[kc][0], qf[kc][1], qf[kc][2], qf[kc][3], b0, b1);
            }

        // online softmax on the 2 rows this thread owns (grp, grp+8)
        #pragma unroll
        for (int rh = 0; rh < 2; rh++){
            float mx = -1e30f;
            #pragma unroll
            for (int nt = 0; nt < 4; nt++)
                mx = fmaxf(mx, fmaxf(sacc[nt][rh*2], sacc[nt][rh*2+1]));
            mx = fmaxf(mx, __shfl_xor_sync(0xffffffffu, mx, 1));
            mx = fmaxf(mx, __shfl_xor_sync(0xffffffffu, mx, 2));
            float mnew = fmaxf(mrun[rh], mx);
            float corr = __expf(mrun[rh] - mnew);
            mrun[rh] = mnew;
            float sum = 0.f;
            #pragma unroll
            for (int nt = 0; nt < 4; nt++){
                float p0 = __expf(sacc[nt][rh*2]   - mnew);
                float p1 = __expf(sacc[nt][rh*2+1] - mnew);
                sacc[nt][rh*2] = p0; sacc[nt][rh*2+1] = p1;
                sum += p0 + p1;
            }
            sum += __shfl_xor_sync(0xffffffffu, sum, 1);
            sum += __shfl_xor_sync(0xffffffffu, sum, 2);
            lrun[rh] = lrun[rh]*corr + sum;
            #pragma unroll
            for (int nt = 0; nt < 8; nt++){
                oacc[nt][rh*2]   *= corr;
                oacc[nt][rh*2+1] *= corr;
            }
        }

        // P -> per-warp smem (tf32)
        #pragma unroll
        for (int nt = 0; nt < 4; nt++){
            Ps[warp][grp  ][nt*8 + 2*tig    ] = f2tf(sacc[nt][0]);
            Ps[warp][grp  ][nt*8 + 2*tig + 1] = f2tf(sacc[nt][1]);
            Ps[warp][grp+8][nt*8 + 2*tig    ] = f2tf(sacc[nt][2]);
            Ps[warp][grp+8][nt*8 + 2*tig + 1] = f2tf(sacc[nt][3]);
        }
        __syncwarp();

        // O += P V : k = 32 keys, n = 64 dh
        #pragma unroll
        for (int kc = 0; kc < 4; kc++){
            uint32_t af0 = Ps[warp][grp  ][kc*8 + tig    ];
            uint32_t af1 = Ps[warp][grp+8][kc*8 + tig    ];
            uint32_t af2 = Ps[warp][grp  ][kc*8 + tig + 4];
            uint32_t af3 = Ps[warp][grp+8][kc*8 + tig + 4];
            #pragma unroll
            for (int nt = 0; nt < 8; nt++){
                uint32_t b0 = Vs[kc*8 + tig    ][nt*8 + grp];
                uint32_t b1 = Vs[kc*8 + tig + 4][nt*8 + grp];
                mma8(oacc[nt], af0, af1, af2, af3, b0, b1);
            }
        }
    }

    float inv0 = 1.f / lrun[0], inv1 = 1.f / lrun[1];
    size_t r0 = ((size_t)(b*SS + qrow + grp    )*HH + h)*DH;
    size_t r1 = ((size_t)(b*SS + qrow + grp + 8)*HH + h)*DH;
    #pragma unroll
    for (int nt = 0; nt < 8; nt++){
        int col = nt*8 + 2*tig;
        *(float2*)(o + r0 + col) = make_float2(oacc[nt][0]*inv0, oacc[nt][1]*inv0);
        *(float2*)(o + r1 + col) = make_float2(oacc[nt][2]*inv1, oacc[nt][3]*inv1);
    }
}

// ---------------------------------------------------------------------------
extern "C" void kernel_launch(void* const* d_in, const int* in_sizes, int n_in,
                              void* d_out, int out_size)
{
    (void)in_sizes; (void)n_in; (void)out_size;
    const float* queries = (const float*)d_in[0];
    const float* keys    = (const float*)d_in[1];
    const float* values  = (const float*)d_in[2];
    const float* Wq = (const float*)d_in[3];
    const float* bq = (const float*)d_in[4];
    const float* Wk = (const float*)d_in[5];
    const float* bk = (const float*)d_in[6];
    const float* Wv = (const float*)d_in[7];
    const float* bv = (const float*)d_in[8];
    const float* Wo = (const float*)d_in[9];
    const float* bo = (const float*)d_in[10];
    float* out = (float*)d_out;

    float *pq, *pk, *pv, *po;
    cudaGetSymbolAddress((void**)&pq, g_q);
    cudaGetSymbolAddress((void**)&pk, g_k);
    cudaGetSymbolAddress((void**)&pv, g_v);
    cudaGetSymbolAddress((void**)&po, g_o);

    dim3 ggrid(8, 64);                 // N/128 x M/128
    gemm_tf32<true><<<ggrid, 256>>>(queries, Wq, bq, pq);
    gemm_tf32<true><<<ggrid, 256>>>(keys,    Wk, bk, pk);
    gemm_tf32<true><<<ggrid, 256>>>(values,  Wv, bv, pv);

    dim3 agrid(SS/64, HH, BB);         // (32, 16, 4)
    attn_tf32<<<agrid, 128>>>(pq, pk, pv, po);

    gemm_tf32<false><<<ggrid, 256>>>(po, Wo, bo, out);
}